// round 15
// baseline (speedup 1.0000x reference)
#include <cuda_runtime.h>
#include <cuda_bf16.h>
#include <cuda_fp16.h>
#include <cstdint>

#define BATCH 8
#define SEQ   2048
#define DIM   512

// ---------------- scratch (allocation-free) ----------------
__device__ __nv_bfloat16 g_xh[(size_t)BATCH * SEQ * DIM];    // x hi (bf16)
__device__ __nv_bfloat16 g_xl[(size_t)BATCH * SEQ * DIM];    // x lo (bf16)
__device__ __nv_bfloat16 g_xwh[(size_t)BATCH * SEQ * DIM];   // xw hi (bf16)
__device__ __nv_bfloat16 g_xwl[(size_t)BATCH * SEQ * DIM];   // xw lo (bf16)
__device__ float         g_prod[(size_t)BATCH * SEQ * SEQ];  // logits (fp32)
__device__ __half        g_pf[(size_t)BATCH * SEQ * SEQ];    // P (fp16, single)
__device__ __nv_bfloat16 g_wth[(size_t)DIM * DIM];           // W^T hi
__device__ __nv_bfloat16 g_wtl[(size_t)DIM * DIM];           // W^T lo
__device__ __half        g_xthf[(size_t)BATCH * SEQ * DIM];  // x^T (fp16, single)

// ---------------- helpers ----------------
__device__ __forceinline__ uint32_t smem_u32(const void* p) {
    uint32_t a;
    asm("{ .reg .u64 t; cvta.to.shared.u64 t, %1; cvt.u32.u64 %0, t; }" : "=r"(a) : "l"(p));
    return a;
}
__device__ __forceinline__ void cp_async16(uint32_t dst, const void* src) {
    asm volatile("cp.async.cg.shared.global [%0], [%1], 16;" :: "r"(dst), "l"(src));
}
#define CP_COMMIT() asm volatile("cp.async.commit_group;" ::: "memory")
#define CP_WAIT(n)  asm volatile("cp.async.wait_group %0;" :: "n"(n) : "memory")

#define LDSM4(r, addr) \
    asm volatile("ldmatrix.sync.aligned.m8n8.x4.shared.b16 {%0,%1,%2,%3}, [%4];" \
                 : "=r"((r)[0]), "=r"((r)[1]), "=r"((r)[2]), "=r"((r)[3]) : "r"(addr))

#define MMA_BF16(c, a, b0, b1) \
    asm volatile("mma.sync.aligned.m16n8k16.row.col.f32.bf16.bf16.f32 " \
                 "{%0,%1,%2,%3}, {%4,%5,%6,%7}, {%8,%9}, {%0,%1,%2,%3};" \
                 : "+f"((c)[0]), "+f"((c)[1]), "+f"((c)[2]), "+f"((c)[3]) \
                 : "r"((a)[0]), "r"((a)[1]), "r"((a)[2]), "r"((a)[3]), "r"(b0), "r"(b1))

#define MMA_F16(c, a, b0, b1) \
    asm volatile("mma.sync.aligned.m16n8k16.row.col.f32.f16.f16.f32 " \
                 "{%0,%1,%2,%3}, {%4,%5,%6,%7}, {%8,%9}, {%0,%1,%2,%3};" \
                 : "+f"((c)[0]), "+f"((c)[1]), "+f"((c)[2]), "+f"((c)[3]) \
                 : "r"((a)[0]), "r"((a)[1]), "r"((a)[2]), "r"((a)[3]), "r"(b0), "r"(b1))

// split fp32 v -> bf16 hi + bf16 lo
__device__ __forceinline__ void split_bf(float v, __nv_bfloat16& h, __nv_bfloat16& l) {
    h = __float2bfloat16_rn(v);
    l = __float2bfloat16_rn(v - __bfloat162float(h));
}

// ---------------- fused-segment 16-bit mma.sync GEMM ----------------
// C[M,N] = alpha * sum_seg( Aseg[M,K] @ Bseg[N,K]^T )
// mode 1 (x3 fused): phase0 = (A_hi,B_hi)+(A_hi,B_lo) with A fragments shared
//   (stage = {Ah,Bh,Bl} 48KB x 2 stages); phase1 = (A_lo,B_hi) (32KB x 3 stages).
//   Phase1 stage0 prefetched in phase0's LAST iteration, after that iteration's
//   CP_WAIT+sync (stage0 smem is dead there: NTk even -> last tile uses stage1).
// mode 0 (x1): phase1 only with A=A_hi  (used for fp16 P @ x).
// Ordering invariant everywhere: CP_WAIT -> __syncthreads -> (issue) -> compute.
#define BM 128
#define BN 128
#define BK 64
#define TILE_BYTES 16384                  // 128 rows x 128B
#define PH0_STAGE  49152                  // 3 tiles
#define PH1_STAGE  32768                  // 2 tiles
#define GEMM_SMEM  98304                  // max(2*PH0, 3*PH1) = 96 KB

template <bool F16>
__global__ __launch_bounds__(256, 2)
void seg_gemm_nt(const uint16_t* __restrict__ Ahi, const uint16_t* __restrict__ Alo,
                 const uint16_t* __restrict__ Bhi, const uint16_t* __restrict__ Blo,
                 void* __restrict__ Cv, void* __restrict__ Clv, int bfOut,
                 int M, int N, int K, int ksh, int mode,
                 long long sA, long long sB, long long sC, float alpha)
{
    extern __shared__ char smem[];
    const uint32_t sb = smem_u32(smem);

    const int tid = threadIdx.x, lane = tid & 31, wid = tid >> 5;
    const int wm = wid >> 2;          // 0..1 : 64-row warp block
    const int wn = wid & 3;           // 0..3 : 32-col warp block
    const int b = blockIdx.z;
    const long long offA = (long long)b * sA;
    const long long offB = (long long)b * sB;
    const long long offC = (long long)b * sC;
    const int row0 = blockIdx.y * BM;
    const int col0 = blockIdx.x * BN;

    const int lrow = tid >> 3;        // 0..31
    const int lseg = tid & 7;         // 16B seg in 128B row

    const int a_ra = (lane & 7) | (((lane >> 3) & 1) << 3);
    const int a_ho = (lane >> 4) << 4;
    const int b_ra = (lane & 7) | (((lane >> 4) & 1) << 3);
    const int b_ho = ((lane >> 3) & 1) << 4;

    float acc[4][4][4];
#pragma unroll
    for (int i = 0; i < 4; i++)
#pragma unroll
        for (int j = 0; j < 4; j++)
#pragma unroll
            for (int v = 0; v < 4; v++) acc[i][j][v] = 0.f;

    const int NTk = 1 << ksh;

    auto cpA = [&](uint32_t dst, const uint16_t* Ap, int kt) {
        const uint16_t* Ag = Ap + offA + (long long)row0 * K + kt * BK;
#pragma unroll
        for (int j = 0; j < 4; j++) {
            int r = lrow + j * 32;
            uint32_t off = (uint32_t)r * 128 + (((uint32_t)lseg * 16) ^ ((r & 7) << 4));
            cp_async16(dst + off, Ag + (long long)r * K + lseg * 8);
        }
    };
    auto cpB = [&](uint32_t dst, const uint16_t* Bp, int kt) {
        const uint16_t* Bg = Bp + offB + (long long)col0 * K + kt * BK;
#pragma unroll
        for (int j = 0; j < 4; j++) {
            int r = lrow + j * 32;
            uint32_t off = (uint32_t)r * 128 + (((uint32_t)lseg * 16) ^ ((r & 7) << 4));
            cp_async16(dst + off, Bg + (long long)r * K + lseg * 8);
        }
    };
    auto ldsmA = [&](uint32_t aB, int ks, uint32_t (&af)[4][4]) {
#pragma unroll
        for (int mt = 0; mt < 4; mt++) {
            int m = wm * 64 + mt * 16 + a_ra;
            uint32_t addr = aB + (uint32_t)m * 128 +
                            (((uint32_t)(a_ho + ks * 32)) ^ ((m & 7) << 4));
            LDSM4(af[mt], addr);
        }
    };
    auto ldsmB = [&](uint32_t bB, int ks, uint32_t (&bf)[2][4]) {
#pragma unroll
        for (int p = 0; p < 2; p++) {
            int n = wn * 32 + p * 16 + b_ra;
            uint32_t addr = bB + (uint32_t)n * 128 +
                            (((uint32_t)(b_ho + ks * 32)) ^ ((n & 7) << 4));
            LDSM4(bf[p], addr);
        }
    };
    auto mma16 = [&](uint32_t (&af)[4][4], uint32_t (&bf)[2][4]) {
#pragma unroll
        for (int mt = 0; mt < 4; mt++)
#pragma unroll
            for (int nt = 0; nt < 4; nt++) {
                if (F16) {
                    MMA_F16(acc[mt][nt], af[mt], bf[nt >> 1][(nt & 1) * 2],
                            bf[nt >> 1][(nt & 1) * 2 + 1]);
                } else {
                    MMA_BF16(acc[mt][nt], af[mt], bf[nt >> 1][(nt & 1) * 2],
                             bf[nt >> 1][(nt & 1) * 2 + 1]);
                }
            }
    };

    // ---- phase 0 (mode 1 only): (A_hi,B_hi) + (A_hi,B_lo), shared A frags ----
    if (mode == 1) {
        cpA(sb, Ahi, 0);
        cpB(sb + TILE_BYTES, Bhi, 0);
        cpB(sb + 2 * TILE_BYTES, Blo, 0);
        CP_COMMIT();
        int kload = 1;
        for (int t = 0; t < NTk; t++) {
            CP_WAIT(0);          // tile t resident (this thread's copies)
            __syncthreads();     // ... and everyone else's; prior readers done
            if (kload < NTk) {
                uint32_t s = sb + (uint32_t)(kload & 1) * PH0_STAGE;
                cpA(s, Ahi, kload);
                cpB(s + TILE_BYTES, Bhi, kload);
                cpB(s + 2 * TILE_BYTES, Blo, kload);
                CP_COMMIT();
                kload++;
            } else {
                // last iteration: prefetch phase1 stage0 into dead stage0 smem [0,32K)
                // (NTk even -> this tile computes from stage1; stage0 readers done)
                cpA(sb, Alo, 0);
                cpB(sb + TILE_BYTES, Bhi, 0);
                CP_COMMIT();
            }
            uint32_t base = sb + (uint32_t)(t & 1) * PH0_STAGE;
#pragma unroll
            for (int ks = 0; ks < 4; ks++) {
                uint32_t af[4][4], bf[2][4];
                ldsmA(base, ks, af);
                ldsmB(base + TILE_BYTES, ks, bf);
                mma16(af, bf);
                ldsmB(base + 2 * TILE_BYTES, ks, bf);   // reuse bf regs (WAR-ordered)
                mma16(af, bf);
            }
        }
        __syncthreads();   // last-tile readers done before overwriting 32K..64K
        // phase1 stage1 load (stage0 already in flight from the prefetch above)
        cpA(sb + PH1_STAGE, Alo, 1);
        cpB(sb + PH1_STAGE + TILE_BYTES, Bhi, 1);
        CP_COMMIT();
    }

    // ---- phase 1: single segment (mode1: (A_lo,B_hi) ; mode0: (A_hi,B_hi)) ----
    // Entry invariant (both modes): exactly {stage0, stage1} groups outstanding.
    {
        const uint16_t* Ap = (mode == 1) ? Alo : Ahi;
        if (mode == 0) {
            cpA(sb, Ap, 0);
            cpB(sb + TILE_BYTES, Bhi, 0);
            CP_COMMIT();
            cpA(sb + PH1_STAGE, Ap, 1);
            cpB(sb + PH1_STAGE + TILE_BYTES, Bhi, 1);
            CP_COMMIT();
        }
        int kload = 2;
        int cs = 0;
        for (int t = 0; t < NTk; t++) {
            CP_WAIT(1);          // tile t resident
            __syncthreads();
            if (kload < NTk) {
                int ls = kload % 3;
                uint32_t s = sb + (uint32_t)ls * PH1_STAGE;
                cpA(s, Ap, kload);
                cpB(s + TILE_BYTES, Bhi, kload);
                CP_COMMIT();
                kload++;
            }
            uint32_t base = sb + (uint32_t)cs * PH1_STAGE;
            cs = (cs + 1 == 3) ? 0 : cs + 1;
#pragma unroll
            for (int ks = 0; ks < 4; ks++) {
                uint32_t af[4][4], bf[2][4];
                ldsmB(base + TILE_BYTES, ks, bf);
                ldsmA(base, ks, af);
                mma16(af, bf);
            }
        }
    }

    // ---- epilogue ----
    const int g = lane >> 2;
    const int qc = (lane & 3) << 1;
#pragma unroll
    for (int mt = 0; mt < 4; mt++) {
#pragma unroll
        for (int nt = 0; nt < 4; nt++) {
            long long r0 = row0 + wm * 64 + mt * 16 + g;
            int cbase = col0 + wn * 32 + nt * 8 + qc;
            float v00 = acc[mt][nt][0] * alpha, v01 = acc[mt][nt][1] * alpha;
            float v10 = acc[mt][nt][2] * alpha, v11 = acc[mt][nt][3] * alpha;
            if (bfOut) {
                __nv_bfloat16* Ch = (__nv_bfloat16*)Cv + offC;
                __nv_bfloat16* Cl = (__nv_bfloat16*)Clv + offC;
                __nv_bfloat162 h2, l2;
                split_bf(v00, h2.x, l2.x); split_bf(v01, h2.y, l2.y);
                *reinterpret_cast<__nv_bfloat162*>(&Ch[r0 * N + cbase]) = h2;
                *reinterpret_cast<__nv_bfloat162*>(&Cl[r0 * N + cbase]) = l2;
                split_bf(v10, h2.x, l2.x); split_bf(v11, h2.y, l2.y);
                *reinterpret_cast<__nv_bfloat162*>(&Ch[(r0 + 8) * N + cbase]) = h2;
                *reinterpret_cast<__nv_bfloat162*>(&Cl[(r0 + 8) * N + cbase]) = l2;
            } else {
                float* C = (float*)Cv + offC;
                *reinterpret_cast<float2*>(&C[r0 * N + cbase]) = make_float2(v00, v01);
                *reinterpret_cast<float2*>(&C[(r0 + 8) * N + cbase]) = make_float2(v10, v11);
            }
        }
    }
}

// ---------------- fused x prep: x -> bf16 xh/xl (direct) + fp16 x^T (transposed) ----
__global__ __launch_bounds__(256)
void prep_x_kernel(const float* __restrict__ in,
                   __nv_bfloat16* __restrict__ hi, __nv_bfloat16* __restrict__ lo,
                   __half* __restrict__ thi,
                   int R, int Ccols)
{
    __shared__ float t[32][33];
    const int b = blockIdx.z;
    const long long base = (long long)b * R * Ccols;
    in += base; hi += base; lo += base; thi += base;
    const int r0 = blockIdx.y * 32, c0 = blockIdx.x * 32;
    const int x = threadIdx.x, y = threadIdx.y;
#pragma unroll
    for (int i = 0; i < 32; i += 8) {
        float v = in[(long long)(r0 + y + i) * Ccols + c0 + x];
        t[y + i][x] = v;
        __nv_bfloat16 h, l;
        split_bf(v, h, l);
        long long o = (long long)(r0 + y + i) * Ccols + c0 + x;
        hi[o] = h;
        lo[o] = l;
    }
    __syncthreads();
#pragma unroll
    for (int i = 0; i < 32; i += 8) {
        long long o = (long long)(c0 + y + i) * R + r0 + x;
        thi[o] = __float2half_rn(t[x][y + i]);
    }
}

// ---------------- transpose + split (for W, bf16) ----------------
__global__ __launch_bounds__(256)
void transpose_split_kernel(const float* __restrict__ in,
                            __nv_bfloat16* __restrict__ hi, __nv_bfloat16* __restrict__ lo,
                            int R, int Ccols)
{
    __shared__ float t[32][33];
    const int r0 = blockIdx.y * 32, c0 = blockIdx.x * 32;
    const int x = threadIdx.x, y = threadIdx.y;
#pragma unroll
    for (int i = 0; i < 32; i += 8)
        t[y + i][x] = in[(long long)(r0 + y + i) * Ccols + c0 + x];
    __syncthreads();
#pragma unroll
    for (int i = 0; i < 32; i += 8) {
        __nv_bfloat16 h, l;
        split_bf(t[x][y + i], h, l);
        long long o = (long long)(c0 + y + i) * R + r0 + x;
        hi[o] = h;
        lo[o] = l;
    }
}

// ---------------- row softmax over 2048 cols: fp32 logits -> fp16 P ----------------
__global__ __launch_bounds__(256)
void softmax2048_kernel(const float* __restrict__ P, __half* __restrict__ Pf)
{
    long long row = blockIdx.x;
    const float* p = P + row * (long long)SEQ;
    const int tid = threadIdx.x;

    const float4* p4 = reinterpret_cast<const float4*>(p);
    float4 v0 = p4[tid];
    float4 v1 = p4[tid + 256];

    float m = fmaxf(fmaxf(fmaxf(v0.x, v0.y), fmaxf(v0.z, v0.w)),
                    fmaxf(fmaxf(v1.x, v1.y), fmaxf(v1.z, v1.w)));
#pragma unroll
    for (int o = 16; o; o >>= 1) m = fmaxf(m, __shfl_xor_sync(0xffffffffu, m, o));

    __shared__ float smax[8];
    __shared__ float ssum[8];
    const int w = tid >> 5, lane = tid & 31;
    if (lane == 0) smax[w] = m;
    __syncthreads();
    float mm = smax[0];
#pragma unroll
    for (int i = 1; i < 8; i++) mm = fmaxf(mm, smax[i]);

    v0.x = __expf(v0.x - mm); v0.y = __expf(v0.y - mm);
    v0.z = __expf(v0.z - mm); v0.w = __expf(v0.w - mm);
    v1.x = __expf(v1.x - mm); v1.y = __expf(v1.y - mm);
    v1.z = __expf(v1.z - mm); v1.w = __expf(v1.w - mm);

    float s = (v0.x + v0.y + v0.z + v0.w) + (v1.x + v1.y + v1.z + v1.w);
#pragma unroll
    for (int o = 16; o; o >>= 1) s += __shfl_xor_sync(0xffffffffu, s, o);
    if (lane == 0) ssum[w] = s;
    __syncthreads();
    float ss = ssum[0];
#pragma unroll
    for (int i = 1; i < 8; i++) ss += ssum[i];
    float inv = __frcp_rn(ss);

    __half2* pf2 = reinterpret_cast<__half2*>(Pf + row * (long long)SEQ);
    pf2[tid * 2]             = __floats2half2_rn(v0.x * inv, v0.y * inv);
    pf2[tid * 2 + 1]         = __floats2half2_rn(v0.z * inv, v0.w * inv);
    pf2[(tid + 256) * 2]     = __floats2half2_rn(v1.x * inv, v1.y * inv);
    pf2[(tid + 256) * 2 + 1] = __floats2half2_rn(v1.z * inv, v1.w * inv);
}

// ---------------- launch ----------------
extern "C" void kernel_launch(void* const* d_in, const int* in_sizes, int n_in,
                              void* d_out, int out_size)
{
    const float* x = (const float*)d_in[0];  // [B, S, D]
    const float* W = (const float*)d_in[1];  // [D, D]
    float* out = (float*)d_out;              // [B, S, D]

    __nv_bfloat16 *xh, *xl, *xwh, *xwl, *wth, *wtl;
    __half *pf, *xthf;
    float* prod;
    cudaGetSymbolAddress((void**)&xh, g_xh);
    cudaGetSymbolAddress((void**)&xl, g_xl);
    cudaGetSymbolAddress((void**)&xwh, g_xwh);
    cudaGetSymbolAddress((void**)&xwl, g_xwl);
    cudaGetSymbolAddress((void**)&prod, g_prod);
    cudaGetSymbolAddress((void**)&pf, g_pf);
    cudaGetSymbolAddress((void**)&wth, g_wth);
    cudaGetSymbolAddress((void**)&wtl, g_wtl);
    cudaGetSymbolAddress((void**)&xthf, g_xthf);

    cudaFuncSetAttribute(seg_gemm_nt<false>, cudaFuncAttributeMaxDynamicSharedMemorySize, GEMM_SMEM);
    cudaFuncSetAttribute(seg_gemm_nt<true>, cudaFuncAttributeMaxDynamicSharedMemorySize, GEMM_SMEM);

    const float inv_sqrt_d = 0.04419417382415922f;  // 1/sqrt(512)

    // prep: x -> bf16 xh/xl + fp16 x^T in one pass; W -> bf16 W^T hi/lo
    prep_x_kernel<<<dim3(DIM / 32, SEQ / 32, BATCH), dim3(32, 8)>>>(x, xh, xl, xthf, SEQ, DIM);
    transpose_split_kernel<<<dim3(DIM / 32, DIM / 32, 1), dim3(32, 8)>>>(W, wth, wtl, DIM, DIM);

    // GEMM1 (bf16x3 fused): xw = x @ W^T'   M=16384, N=512, K=512 (ksh=3); bf16 split out
    seg_gemm_nt<false><<<dim3(DIM / BN, (BATCH * SEQ) / BM, 1), 256, GEMM_SMEM>>>(
        (const uint16_t*)xh, (const uint16_t*)xl, (const uint16_t*)wth, (const uint16_t*)wtl,
        xwh, xwl, 1,
        BATCH * SEQ, DIM, DIM, 3, 1, 0, 0, 0, 1.0f);

    // GEMM2 (bf16x3 fused): prod[b] = (xw[b] @ x[b]^T)/sqrt(D)   M=N=2048, K=512 (ksh=3)
    seg_gemm_nt<false><<<dim3(SEQ / BN, SEQ / BM, BATCH), 256, GEMM_SMEM>>>(
        (const uint16_t*)xwh, (const uint16_t*)xwl, (const uint16_t*)xh, (const uint16_t*)xl,
        prod, nullptr, 0,
        SEQ, SEQ, DIM, 3, 1,
        (long long)SEQ * DIM, (long long)SEQ * DIM, (long long)SEQ * SEQ, inv_sqrt_d);

    // softmax rows: fp32 logits -> fp16 P (single array)
    softmax2048_kernel<<<BATCH * SEQ, 256>>>(prod, pf);

    // GEMM3 (fp16 x1): out[b] = P[b] @ x[b]   M=2048, N=512, K=2048 (ksh=5, mode 0)
    seg_gemm_nt<true><<<dim3(DIM / BN, SEQ / BM, BATCH), 256, GEMM_SMEM>>>(
        (const uint16_t*)pf, (const uint16_t*)pf, (const uint16_t*)xthf, (const uint16_t*)xthf,
        out, nullptr, 0,
        SEQ, DIM, SEQ, 5, 0,
        (long long)SEQ * SEQ, (long long)SEQ * DIM, (long long)SEQ * DIM, 1.0f);
}

// round 16
// speedup vs baseline: 1.0380x; 1.0380x over previous
#include <cuda_runtime.h>
#include <cuda_bf16.h>
#include <cuda_fp16.h>
#include <cstdint>

#define BATCH 8
#define SEQ   2048
#define DIM   512

// ---------------- scratch (allocation-free) ----------------
__device__ __nv_bfloat16 g_xh[(size_t)BATCH * SEQ * DIM];    // x hi (bf16)
__device__ __nv_bfloat16 g_xl[(size_t)BATCH * SEQ * DIM];    // x lo (bf16)
__device__ __nv_bfloat16 g_xwh[(size_t)BATCH * SEQ * DIM];   // xw hi (bf16)
__device__ __nv_bfloat16 g_xwl[(size_t)BATCH * SEQ * DIM];   // xw lo (bf16)
__device__ float         g_prod[(size_t)BATCH * SEQ * SEQ];  // logits (fp32)
__device__ __half        g_pf[(size_t)BATCH * SEQ * SEQ];    // P (fp16, single)
__device__ __nv_bfloat16 g_wth[(size_t)DIM * DIM];           // W^T hi
__device__ __nv_bfloat16 g_wtl[(size_t)DIM * DIM];           // W^T lo
__device__ __half        g_xthf[(size_t)BATCH * SEQ * DIM];  // x^T (fp16, single)

// ---------------- helpers ----------------
__device__ __forceinline__ uint32_t smem_u32(const void* p) {
    uint32_t a;
    asm("{ .reg .u64 t; cvta.to.shared.u64 t, %1; cvt.u32.u64 %0, t; }" : "=r"(a) : "l"(p));
    return a;
}
__device__ __forceinline__ void cp_async16(uint32_t dst, const void* src) {
    asm volatile("cp.async.cg.shared.global [%0], [%1], 16;" :: "r"(dst), "l"(src));
}
#define CP_COMMIT() asm volatile("cp.async.commit_group;" ::: "memory")
#define CP_WAIT(n)  asm volatile("cp.async.wait_group %0;" :: "n"(n) : "memory")

#define LDSM4(r, addr) \
    asm volatile("ldmatrix.sync.aligned.m8n8.x4.shared.b16 {%0,%1,%2,%3}, [%4];" \
                 : "=r"((r)[0]), "=r"((r)[1]), "=r"((r)[2]), "=r"((r)[3]) : "r"(addr))

#define MMA_BF16(c, a, b0, b1) \
    asm volatile("mma.sync.aligned.m16n8k16.row.col.f32.bf16.bf16.f32 " \
                 "{%0,%1,%2,%3}, {%4,%5,%6,%7}, {%8,%9}, {%0,%1,%2,%3};" \
                 : "+f"((c)[0]), "+f"((c)[1]), "+f"((c)[2]), "+f"((c)[3]) \
                 : "r"((a)[0]), "r"((a)[1]), "r"((a)[2]), "r"((a)[3]), "r"(b0), "r"(b1))

#define MMA_F16(c, a, b0, b1) \
    asm volatile("mma.sync.aligned.m16n8k16.row.col.f32.f16.f16.f32 " \
                 "{%0,%1,%2,%3}, {%4,%5,%6,%7}, {%8,%9}, {%0,%1,%2,%3};" \
                 : "+f"((c)[0]), "+f"((c)[1]), "+f"((c)[2]), "+f"((c)[3]) \
                 : "r"((a)[0]), "r"((a)[1]), "r"((a)[2]), "r"((a)[3]), "r"(b0), "r"(b1))

// split fp32 v -> bf16 hi + bf16 lo
__device__ __forceinline__ void split_bf(float v, __nv_bfloat16& h, __nv_bfloat16& l) {
    h = __float2bfloat16_rn(v);
    l = __float2bfloat16_rn(v - __bfloat162float(h));
}

// ---------------- fused-segment 16-bit mma.sync GEMM ----------------
// C[M,N] = alpha * sum_seg( Aseg[M,K] @ Bseg[N,K]^T )
// mode 1 (x3 fused): phase0 = (A_hi,B_hi)+(A_hi,B_lo) with A fragments shared
//   (stage = {Ah,Bh,Bl} 48KB x 2 stages); phase1 = (A_lo,B_hi) (32KB x 3 stages).
// mode 0 (x1): phase1 only with A=A_hi  (used for fp16 P @ x).
// Ordering invariant (R13-proven): CP_WAIT -> __syncthreads -> issue -> compute.
#define BM 128
#define BN 128
#define BK 64
#define TILE_BYTES 16384                  // 128 rows x 128B
#define PH0_STAGE  49152                  // 3 tiles
#define PH1_STAGE  32768                  // 2 tiles
#define GEMM_SMEM  98304                  // max(2*PH0, 3*PH1) = 96 KB

template <bool F16>
__global__ __launch_bounds__(256, 2)
void seg_gemm_nt(const uint16_t* __restrict__ Ahi, const uint16_t* __restrict__ Alo,
                 const uint16_t* __restrict__ Bhi, const uint16_t* __restrict__ Blo,
                 void* __restrict__ Cv, void* __restrict__ Clv, int bfOut,
                 int M, int N, int K, int ksh, int mode,
                 long long sA, long long sB, long long sC, float alpha)
{
    extern __shared__ char smem[];
    const uint32_t sb = smem_u32(smem);

    const int tid = threadIdx.x, lane = tid & 31, wid = tid >> 5;
    const int wm = wid >> 2;          // 0..1 : 64-row warp block
    const int wn = wid & 3;           // 0..3 : 32-col warp block
    const int b = blockIdx.z;
    const long long offA = (long long)b * sA;
    const long long offB = (long long)b * sB;
    const long long offC = (long long)b * sC;
    const int row0 = blockIdx.y * BM;
    const int col0 = blockIdx.x * BN;

    const int lrow = tid >> 3;        // 0..31
    const int lseg = tid & 7;         // 16B seg in 128B row

    const int a_ra = (lane & 7) | (((lane >> 3) & 1) << 3);
    const int a_ho = (lane >> 4) << 4;
    const int b_ra = (lane & 7) | (((lane >> 4) & 1) << 3);
    const int b_ho = ((lane >> 3) & 1) << 4;

    float acc[4][4][4];
#pragma unroll
    for (int i = 0; i < 4; i++)
#pragma unroll
        for (int j = 0; j < 4; j++)
#pragma unroll
            for (int v = 0; v < 4; v++) acc[i][j][v] = 0.f;

    const int NTk = 1 << ksh;

    auto cpA = [&](uint32_t dst, const uint16_t* Ap, int kt) {
        const uint16_t* Ag = Ap + offA + (long long)row0 * K + kt * BK;
#pragma unroll
        for (int j = 0; j < 4; j++) {
            int r = lrow + j * 32;
            uint32_t off = (uint32_t)r * 128 + (((uint32_t)lseg * 16) ^ ((r & 7) << 4));
            cp_async16(dst + off, Ag + (long long)r * K + lseg * 8);
        }
    };
    auto cpB = [&](uint32_t dst, const uint16_t* Bp, int kt) {
        const uint16_t* Bg = Bp + offB + (long long)col0 * K + kt * BK;
#pragma unroll
        for (int j = 0; j < 4; j++) {
            int r = lrow + j * 32;
            uint32_t off = (uint32_t)r * 128 + (((uint32_t)lseg * 16) ^ ((r & 7) << 4));
            cp_async16(dst + off, Bg + (long long)r * K + lseg * 8);
        }
    };
    auto ldsmA = [&](uint32_t aB, int ks, uint32_t (&af)[4][4]) {
#pragma unroll
        for (int mt = 0; mt < 4; mt++) {
            int m = wm * 64 + mt * 16 + a_ra;
            uint32_t addr = aB + (uint32_t)m * 128 +
                            (((uint32_t)(a_ho + ks * 32)) ^ ((m & 7) << 4));
            LDSM4(af[mt], addr);
        }
    };
    auto ldsmB = [&](uint32_t bB, int ks, uint32_t (&bf)[2][4]) {
#pragma unroll
        for (int p = 0; p < 2; p++) {
            int n = wn * 32 + p * 16 + b_ra;
            uint32_t addr = bB + (uint32_t)n * 128 +
                            (((uint32_t)(b_ho + ks * 32)) ^ ((n & 7) << 4));
            LDSM4(bf[p], addr);
        }
    };
    auto mma16 = [&](uint32_t (&af)[4][4], uint32_t (&bf)[2][4]) {
#pragma unroll
        for (int mt = 0; mt < 4; mt++)
#pragma unroll
            for (int nt = 0; nt < 4; nt++) {
                if (F16) {
                    MMA_F16(acc[mt][nt], af[mt], bf[nt >> 1][(nt & 1) * 2],
                            bf[nt >> 1][(nt & 1) * 2 + 1]);
                } else {
                    MMA_BF16(acc[mt][nt], af[mt], bf[nt >> 1][(nt & 1) * 2],
                             bf[nt >> 1][(nt & 1) * 2 + 1]);
                }
            }
    };

    // ---- phase 0 (mode 1 only): (A_hi,B_hi) + (A_hi,B_lo), shared A frags ----
    if (mode == 1) {
        cpA(sb, Ahi, 0);
        cpB(sb + TILE_BYTES, Bhi, 0);
        cpB(sb + 2 * TILE_BYTES, Blo, 0);
        CP_COMMIT();
        int kload = 1;
        for (int t = 0; t < NTk; t++) {
            CP_WAIT(0);          // tile t resident (this thread's copies)
            __syncthreads();     // ... everyone's copies visible; prior readers done
            if (kload < NTk) {
                uint32_t s = sb + (uint32_t)(kload & 1) * PH0_STAGE;
                cpA(s, Ahi, kload);
                cpB(s + TILE_BYTES, Bhi, kload);
                cpB(s + 2 * TILE_BYTES, Blo, kload);
                CP_COMMIT();
                kload++;
            }
            uint32_t base = sb + (uint32_t)(t & 1) * PH0_STAGE;
#pragma unroll
            for (int ks = 0; ks < 4; ks++) {
                uint32_t af[4][4], bf[2][4];
                ldsmB(base + TILE_BYTES, ks, bf);    // short batch first: gating
                ldsmA(base, ks, af);                 // fragment (af) issues earlier
                mma16(af, bf);
                ldsmB(base + 2 * TILE_BYTES, ks, bf);   // reuse bf regs (WAR-ordered)
                mma16(af, bf);
            }
        }
        __syncthreads();   // phase1 loads overwrite phase0 smem
    }

    // ---- phase 1: single segment (mode1: (A_lo,B_hi) ; mode0: (A_hi,B_hi)) ----
    {
        const uint16_t* Ap = (mode == 1) ? Alo : Ahi;
        cpA(sb, Ap, 0);
        cpB(sb + TILE_BYTES, Bhi, 0);
        CP_COMMIT();
        cpA(sb + PH1_STAGE, Ap, 1);
        cpB(sb + PH1_STAGE + TILE_BYTES, Bhi, 1);
        CP_COMMIT();
        int kload = 2;
        int cs = 0;
        for (int t = 0; t < NTk; t++) {
            CP_WAIT(1);
            __syncthreads();
            if (kload < NTk) {
                int ls = kload % 3;
                uint32_t s = sb + (uint32_t)ls * PH1_STAGE;
                cpA(s, Ap, kload);
                cpB(s + TILE_BYTES, Bhi, kload);
                CP_COMMIT();
                kload++;
            }
            uint32_t base = sb + (uint32_t)cs * PH1_STAGE;
            cs = (cs + 1 == 3) ? 0 : cs + 1;
#pragma unroll
            for (int ks = 0; ks < 4; ks++) {
                uint32_t af[4][4], bf[2][4];
                ldsmB(base + TILE_BYTES, ks, bf);
                ldsmA(base, ks, af);
                mma16(af, bf);
            }
        }
    }

    // ---- epilogue ----
    const int g = lane >> 2;
    const int qc = (lane & 3) << 1;
#pragma unroll
    for (int mt = 0; mt < 4; mt++) {
#pragma unroll
        for (int nt = 0; nt < 4; nt++) {
            long long r0 = row0 + wm * 64 + mt * 16 + g;
            int cbase = col0 + wn * 32 + nt * 8 + qc;
            float v00 = acc[mt][nt][0] * alpha, v01 = acc[mt][nt][1] * alpha;
            float v10 = acc[mt][nt][2] * alpha, v11 = acc[mt][nt][3] * alpha;
            if (bfOut) {
                __nv_bfloat16* Ch = (__nv_bfloat16*)Cv + offC;
                __nv_bfloat16* Cl = (__nv_bfloat16*)Clv + offC;
                __nv_bfloat162 h2, l2;
                split_bf(v00, h2.x, l2.x); split_bf(v01, h2.y, l2.y);
                *reinterpret_cast<__nv_bfloat162*>(&Ch[r0 * N + cbase]) = h2;
                *reinterpret_cast<__nv_bfloat162*>(&Cl[r0 * N + cbase]) = l2;
                split_bf(v10, h2.x, l2.x); split_bf(v11, h2.y, l2.y);
                *reinterpret_cast<__nv_bfloat162*>(&Ch[(r0 + 8) * N + cbase]) = h2;
                *reinterpret_cast<__nv_bfloat162*>(&Cl[(r0 + 8) * N + cbase]) = l2;
            } else {
                float* C = (float*)Cv + offC;
                *reinterpret_cast<float2*>(&C[r0 * N + cbase]) = make_float2(v00, v01);
                *reinterpret_cast<float2*>(&C[(r0 + 8) * N + cbase]) = make_float2(v10, v11);
            }
        }
    }
}

// ---------------- fused x prep: x -> bf16 xh/xl (direct) + fp16 x^T (transposed) ----
__global__ __launch_bounds__(256)
void prep_x_kernel(const float* __restrict__ in,
                   __nv_bfloat16* __restrict__ hi, __nv_bfloat16* __restrict__ lo,
                   __half* __restrict__ thi,
                   int R, int Ccols)
{
    __shared__ float t[32][33];
    const int b = blockIdx.z;
    const long long base = (long long)b * R * Ccols;
    in += base; hi += base; lo += base; thi += base;
    const int r0 = blockIdx.y * 32, c0 = blockIdx.x * 32;
    const int x = threadIdx.x, y = threadIdx.y;
#pragma unroll
    for (int i = 0; i < 32; i += 8) {
        float v = in[(long long)(r0 + y + i) * Ccols + c0 + x];
        t[y + i][x] = v;
        __nv_bfloat16 h, l;
        split_bf(v, h, l);
        long long o = (long long)(r0 + y + i) * Ccols + c0 + x;
        hi[o] = h;
        lo[o] = l;
    }
    __syncthreads();
#pragma unroll
    for (int i = 0; i < 32; i += 8) {
        long long o = (long long)(c0 + y + i) * R + r0 + x;
        thi[o] = __float2half_rn(t[x][y + i]);
    }
}

// ---------------- transpose + split (for W, bf16) ----------------
__global__ __launch_bounds__(256)
void transpose_split_kernel(const float* __restrict__ in,
                            __nv_bfloat16* __restrict__ hi, __nv_bfloat16* __restrict__ lo,
                            int R, int Ccols)
{
    __shared__ float t[32][33];
    const int r0 = blockIdx.y * 32, c0 = blockIdx.x * 32;
    const int x = threadIdx.x, y = threadIdx.y;
#pragma unroll
    for (int i = 0; i < 32; i += 8)
        t[y + i][x] = in[(long long)(r0 + y + i) * Ccols + c0 + x];
    __syncthreads();
#pragma unroll
    for (int i = 0; i < 32; i += 8) {
        __nv_bfloat16 h, l;
        split_bf(t[x][y + i], h, l);
        long long o = (long long)(c0 + y + i) * R + r0 + x;
        hi[o] = h;
        lo[o] = l;
    }
}

// ---------------- row softmax over 2048 cols: fp32 logits -> fp16 P ----------------
__global__ __launch_bounds__(256)
void softmax2048_kernel(const float* __restrict__ P, __half* __restrict__ Pf)
{
    long long row = blockIdx.x;
    const float* p = P + row * (long long)SEQ;
    const int tid = threadIdx.x;

    const float4* p4 = reinterpret_cast<const float4*>(p);
    float4 v0 = p4[tid];
    float4 v1 = p4[tid + 256];

    float m = fmaxf(fmaxf(fmaxf(v0.x, v0.y), fmaxf(v0.z, v0.w)),
                    fmaxf(fmaxf(v1.x, v1.y), fmaxf(v1.z, v1.w)));
#pragma unroll
    for (int o = 16; o; o >>= 1) m = fmaxf(m, __shfl_xor_sync(0xffffffffu, m, o));

    __shared__ float smax[8];
    __shared__ float ssum[8];
    const int w = tid >> 5, lane = tid & 31;
    if (lane == 0) smax[w] = m;
    __syncthreads();
    float mm = smax[0];
#pragma unroll
    for (int i = 1; i < 8; i++) mm = fmaxf(mm, smax[i]);

    v0.x = __expf(v0.x - mm); v0.y = __expf(v0.y - mm);
    v0.z = __expf(v0.z - mm); v0.w = __expf(v0.w - mm);
    v1.x = __expf(v1.x - mm); v1.y = __expf(v1.y - mm);
    v1.z = __expf(v1.z - mm); v1.w = __expf(v1.w - mm);

    float s = (v0.x + v0.y + v0.z + v0.w) + (v1.x + v1.y + v1.z + v1.w);
#pragma unroll
    for (int o = 16; o; o >>= 1) s += __shfl_xor_sync(0xffffffffu, s, o);
    if (lane == 0) ssum[w] = s;
    __syncthreads();
    float ss = ssum[0];
#pragma unroll
    for (int i = 1; i < 8; i++) ss += ssum[i];
    float inv = __frcp_rn(ss);

    __half2* pf2 = reinterpret_cast<__half2*>(Pf + row * (long long)SEQ);
    pf2[tid * 2]             = __floats2half2_rn(v0.x * inv, v0.y * inv);
    pf2[tid * 2 + 1]         = __floats2half2_rn(v0.z * inv, v0.w * inv);
    pf2[(tid + 256) * 2]     = __floats2half2_rn(v1.x * inv, v1.y * inv);
    pf2[(tid + 256) * 2 + 1] = __floats2half2_rn(v1.z * inv, v1.w * inv);
}

// ---------------- launch ----------------
extern "C" void kernel_launch(void* const* d_in, const int* in_sizes, int n_in,
                              void* d_out, int out_size)
{
    const float* x = (const float*)d_in[0];  // [B, S, D]
    const float* W = (const float*)d_in[1];  // [D, D]
    float* out = (float*)d_out;              // [B, S, D]

    __nv_bfloat16 *xh, *xl, *xwh, *xwl, *wth, *wtl;
    __half *pf, *xthf;
    float* prod;
    cudaGetSymbolAddress((void**)&xh, g_xh);
    cudaGetSymbolAddress((void**)&xl, g_xl);
    cudaGetSymbolAddress((void**)&xwh, g_xwh);
    cudaGetSymbolAddress((void**)&xwl, g_xwl);
    cudaGetSymbolAddress((void**)&prod, g_prod);
    cudaGetSymbolAddress((void**)&pf, g_pf);
    cudaGetSymbolAddress((void**)&wth, g_wth);
    cudaGetSymbolAddress((void**)&wtl, g_wtl);
    cudaGetSymbolAddress((void**)&xthf, g_xthf);

    cudaFuncSetAttribute(seg_gemm_nt<false>, cudaFuncAttributeMaxDynamicSharedMemorySize, GEMM_SMEM);
    cudaFuncSetAttribute(seg_gemm_nt<true>, cudaFuncAttributeMaxDynamicSharedMemorySize, GEMM_SMEM);

    const float inv_sqrt_d = 0.04419417382415922f;  // 1/sqrt(512)

    // prep: x -> bf16 xh/xl + fp16 x^T in one pass; W -> bf16 W^T hi/lo
    prep_x_kernel<<<dim3(DIM / 32, SEQ / 32, BATCH), dim3(32, 8)>>>(x, xh, xl, xthf, SEQ, DIM);
    transpose_split_kernel<<<dim3(DIM / 32, DIM / 32, 1), dim3(32, 8)>>>(W, wth, wtl, DIM, DIM);

    // GEMM1 (bf16x3 fused): xw = x @ W^T'   M=16384, N=512, K=512 (ksh=3); bf16 split out
    seg_gemm_nt<false><<<dim3(DIM / BN, (BATCH * SEQ) / BM, 1), 256, GEMM_SMEM>>>(
        (const uint16_t*)xh, (const uint16_t*)xl, (const uint16_t*)wth, (const uint16_t*)wtl,
        xwh, xwl, 1,
        BATCH * SEQ, DIM, DIM, 3, 1, 0, 0, 0, 1.0f);

    // GEMM2 (bf16x3 fused): prod[b] = (xw[b] @ x[b]^T)/sqrt(D)   M=N=2048, K=512 (ksh=3)
    seg_gemm_nt<false><<<dim3(SEQ / BN, SEQ / BM, BATCH), 256, GEMM_SMEM>>>(
        (const uint16_t*)xwh, (const uint16_t*)xwl, (const uint16_t*)xh, (const uint16_t*)xl,
        prod, nullptr, 0,
        SEQ, SEQ, DIM, 3, 1,
        (long long)SEQ * DIM, (long long)SEQ * DIM, (long long)SEQ * SEQ, inv_sqrt_d);

    // softmax rows: fp32 logits -> fp16 P (single array)
    softmax2048_kernel<<<BATCH * SEQ, 256>>>(prod, pf);

    // GEMM3 (fp16 x1): out[b] = P[b] @ x[b]   M=2048, N=512, K=2048 (ksh=5, mode 0)
    seg_gemm_nt<true><<<dim3(DIM / BN, SEQ / BM, BATCH), 256, GEMM_SMEM>>>(
        (const uint16_t*)pf, (const uint16_t*)pf, (const uint16_t*)xthf, (const uint16_t*)xthf,
        out, nullptr, 0,
        SEQ, DIM, SEQ, 5, 0,
        (long long)SEQ * SEQ, (long long)SEQ * DIM, (long long)SEQ * DIM, 1.0f);
}